// round 8
// baseline (speedup 1.0000x reference)
#include <cuda_runtime.h>
#include <cuda_bf16.h>
#include <cstdint>

// lstm_model_8873402433789 R8 — mma.sync bf16 LSTM, CTA-decoupled.
// 512 CTAs x 16 rows x 64 threads (one warp-pair). Multiple independent CTAs
// per SMSP anti-phase tensor vs MUFU work. Double-buffered h (1 barrier/step),
// warp-private double-buffered x (x-MMAs issue pre-barrier).

#define TT 200
#define CROWS 16
#define DD 60
#define KSW 104      // weight smem row stride (bf16 elems)
#define HSTR 136     // h row stride: buf0 [hi 0-31|lo 32-63] buf1 [64-127] pad
#define XSTR 72      // x row stride: buf0 [hi 0-15|lo 16-31] buf1 [32-63] pad
#define HBYTES (CROWS * HSTR * 2)                 // 4352
#define XBYTES (2 * CROWS * XSTR * 2)             // 4608
#define WBYTES (128 * KSW * 2)                    // 26624
#define SMEM_BYTES WBYTES                         // loop overlay (h+x) fits inside

static __device__ __forceinline__ uint32_t s2u(const void* p) {
    uint32_t a;
    asm("{ .reg .u64 t; cvta.to.shared.u64 t, %1; cvt.u32.u64 %0, t; }"
        : "=r"(a) : "l"(p));
    return a;
}
static __device__ __forceinline__ float bhi(float a) {
    return __bfloat162float(__float2bfloat16_rn(a));
}
static __device__ __forceinline__ uint32_t bpack(float a, float b) {
    __nv_bfloat162 t = __float22bfloat162_rn(make_float2(a, b));
    return *(uint32_t*)&t;
}
static __device__ __forceinline__ float ex2n(float g) {   // exp(-g)
    float e;
    asm("ex2.approx.f32 %0, %1;" : "=f"(e) : "f"(-1.4426950408889634f * g));
    return e;
}
static __device__ __forceinline__ float frcp(float a) {
    float r;
    asm("rcp.approx.f32 %0, %1;" : "=f"(r) : "f"(a));
    return r;
}
static __device__ __forceinline__ void ldsm4(uint32_t* r, uint32_t addr) {
    asm volatile("ldmatrix.sync.aligned.m8n8.x4.shared.b16 {%0,%1,%2,%3}, [%4];"
                 : "=r"(r[0]), "=r"(r[1]), "=r"(r[2]), "=r"(r[3]) : "r"(addr));
}
static __device__ __forceinline__ void mma16816(float* d, const uint32_t* a,
                                                const uint32_t* b) {
    asm volatile(
        "mma.sync.aligned.m16n8k16.row.col.f32.bf16.bf16.f32 "
        "{%0,%1,%2,%3}, {%4,%5,%6,%7}, {%8,%9}, {%0,%1,%2,%3};"
        : "+f"(d[0]), "+f"(d[1]), "+f"(d[2]), "+f"(d[3])
        : "r"(a[0]), "r"(a[1]), "r"(a[2]), "r"(a[3]), "r"(b[0]), "r"(b[1]));
}

__global__ void __launch_bounds__(64, 4) lstm_mma4_kernel(
    const float* __restrict__ x,  const float* __restrict__ W,
    const float* __restrict__ U,  const float* __restrict__ b,
    const float* __restrict__ W1, const float* __restrict__ b1,
    const float* __restrict__ W2, const float* __restrict__ b2,
    float* __restrict__ out)
{
    __shared__ __align__(16) char SMEM[SMEM_BYTES];
    __nv_bfloat16* wsm = (__nv_bfloat16*)SMEM;            // init only
    __nv_bfloat16* hsm = (__nv_bfloat16*)SMEM;            // loop: h [16][HSTR]
    __nv_bfloat16* xpr = (__nv_bfloat16*)(SMEM + HBYTES); // loop: x [2w][16][XSTR]

    const int tid = threadIdx.x;
    const int l   = tid & 31;
    const int mg  = tid >> 5;     // unit half (also warp id)
    const int gid = l >> 2, tig = l & 3;

    // ---- weights -> wsm  [Uhi 0-31 | Ulo 32-63 | Whi 64-79 | Wlo 80-95]
    for (int idx = tid; idx < 128 * 96; idx += 64) {
        int g = idx / 96, k = idx - g * 96;
        float v;
        if (k < 32)      v = bhi(U[k * 128 + g]);
        else if (k < 64) { float u = U[(k - 32) * 128 + g]; v = u - bhi(u); }
        else if (k < 80) v = bhi(W[(k - 64) * 128 + g]);
        else             { float t = W[(k - 80) * 128 + g]; v = t - bhi(t); }
        wsm[g * KSW + k] = __float2bfloat16_rn(v);
    }
    __syncthreads();

    // ---- A fragments: afr[mt][ks 0..5][4]  (Uhi:0,1 Ulo:2,3 Whi:4 Wlo:5)
    const uint32_t wsmu = s2u(wsm);
    uint32_t afr[4][6][4];
    {
        int laneRow = (l & 7) + 8 * ((l >> 3) & 1);
        int laneK   = 8 * (l >> 4);
#pragma unroll
        for (int mt = 0; mt < 4; ++mt) {
            int Gmt = 32 * mt + 16 * mg;
#pragma unroll
            for (int ks = 0; ks < 6; ++ks)
                ldsm4(afr[mt][ks], wsmu + ((Gmt + laneRow) * KSW + 16 * ks + laneK) * 2);
        }
    }
    float bv[4][2];
#pragma unroll
    for (int mt = 0; mt < 4; ++mt) {
        bv[mt][0] = b[32 * mt + 16 * mg + gid];
        bv[mt][1] = b[32 * mt + 16 * mg + gid + 8];
    }
    __syncthreads();   // wsm dead -> h + x overlay

    // ---- zero h buf0; stage x(0) privately; prefetch x(1)
    for (int idx = tid; idx < CROWS * 64; idx += 64) {
        int rr = idx >> 6, cc = idx & 63;
        hsm[rr * HSTR + cc] = __float2bfloat16_rn(0.0f);
    }
    const int prow = l >> 1, pseg = l & 1;   // 32 lanes: 16 rows x 2 segs
    const float4* xg = (const float4*)(x +
        ((size_t)blockIdx.x * CROWS + prow) * (TT * 16) + pseg * 8);
    __nv_bfloat16* xmy = xpr + (mg * CROWS + prow) * XSTR;
    {
        float4 v0 = xg[0], v1 = xg[1];   // x(0)
        *(uint4*)(xmy + pseg * 8) =
            make_uint4(bpack(v0.x, v0.y), bpack(v0.z, v0.w),
                       bpack(v1.x, v1.y), bpack(v1.z, v1.w));
        *(uint4*)(xmy + 16 + pseg * 8) =
            make_uint4(bpack(v0.x - bhi(v0.x), v0.y - bhi(v0.y)),
                       bpack(v0.z - bhi(v0.z), v0.w - bhi(v0.w)),
                       bpack(v1.x - bhi(v1.x), v1.y - bhi(v1.y)),
                       bpack(v1.z - bhi(v1.z), v1.w - bhi(v1.w)));
    }
    float4 pf0 = xg[4], pf1 = xg[5];     // x(1)
    __syncthreads();

    const uint32_t hbu = s2u(hsm);
    const uint32_t xbu = s2u(xpr + mg * CROWS * XSTR);
    const int lr8 = l & 7, lq = (l >> 3) & 3;

    uint32_t xf[2][4];
    ldsm4(xf[0], xbu + ((0 * 8 + lr8) * XSTR + lq * 8) * 2);
    ldsm4(xf[1], xbu + ((1 * 8 + lr8) * XSTR + lq * 8) * 2);

    float cst[2][2][2], hrg[2][2][2];
#pragma unroll
    for (int i = 0; i < 2; ++i)
#pragma unroll
        for (int j = 0; j < 2; ++j)
#pragma unroll
            for (int k = 0; k < 2; ++k) { cst[i][j][k] = 0.0f; hrg[i][j][k] = 0.0f; }

#pragma unroll 1
    for (int t = 0; t < TT; ++t) {
        const int p = t & 1, pn = p ^ 1;

        // ---- x-MMAs (pre-barrier, private xf)
        float dac[4][2][4];
#pragma unroll
        for (int mt = 0; mt < 4; ++mt)
#pragma unroll
            for (int nt = 0; nt < 2; ++nt) {
                dac[mt][nt][0] = bv[mt][0]; dac[mt][nt][1] = bv[mt][0];
                dac[mt][nt][2] = bv[mt][1]; dac[mt][nt][3] = bv[mt][1];
            }
#pragma unroll
        for (int mt = 0; mt < 4; ++mt)
#pragma unroll
            for (int nt = 0; nt < 2; ++nt) {
                float* d = dac[mt][nt];
                mma16816(d, afr[mt][4], &xf[nt][0]);   // Whi . x_hi
                mma16816(d, afr[mt][4], &xf[nt][2]);   // Whi . x_lo
                mma16816(d, afr[mt][5], &xf[nt][0]);   // Wlo . x_hi
            }

        // ---- pair barrier: h(t) visible
        __syncthreads();

        // ---- h fragments from buf p, then h-MMAs
        uint32_t bhh[2][4], bhl[2][4];
#pragma unroll
        for (int nt = 0; nt < 2; ++nt) {
            uint32_t rowoff = ((nt * 8 + lr8) * HSTR + p * 64 + lq * 8) * 2;
            ldsm4(bhh[nt], hbu + rowoff);
            ldsm4(bhl[nt], hbu + rowoff + 64);
        }
#pragma unroll
        for (int mt = 0; mt < 4; ++mt)
#pragma unroll
            for (int nt = 0; nt < 2; ++nt) {
                float* d = dac[mt][nt];
                mma16816(d, afr[mt][0], &bhh[nt][0]);  // Uhi . h_hi
                mma16816(d, afr[mt][1], &bhh[nt][2]);
                mma16816(d, afr[mt][0], &bhl[nt][0]);  // Uhi . h_lo
                mma16816(d, afr[mt][1], &bhl[nt][2]);
                mma16816(d, afr[mt][2], &bhh[nt][0]);  // Ulo . h_hi
                mma16816(d, afr[mt][3], &bhh[nt][2]);
            }

        // ---- stage x(t+1) -> buf pn; prefetch x(t+2); ldsm xf(t+1)
        {
            *(uint4*)(xmy + pn * 32 + pseg * 8) =
                make_uint4(bpack(pf0.x, pf0.y), bpack(pf0.z, pf0.w),
                           bpack(pf1.x, pf1.y), bpack(pf1.z, pf1.w));
            *(uint4*)(xmy + pn * 32 + 16 + pseg * 8) =
                make_uint4(bpack(pf0.x - bhi(pf0.x), pf0.y - bhi(pf0.y)),
                           bpack(pf0.z - bhi(pf0.z), pf0.w - bhi(pf0.w)),
                           bpack(pf1.x - bhi(pf1.x), pf1.y - bhi(pf1.y)),
                           bpack(pf1.z - bhi(pf1.z), pf1.w - bhi(pf1.w)));
            int tn = (t + 2 < TT) ? t + 2 : TT - 1;
            pf0 = xg[tn * 4]; pf1 = xg[tn * 4 + 1];
            __syncwarp();
            ldsm4(xf[0], xbu + ((0 * 8 + lr8) * XSTR + pn * 32 + lq * 8) * 2);
            ldsm4(xf[1], xbu + ((1 * 8 + lr8) * XSTR + pn * 32 + lq * 8) * 2);
        }

        // ---- state update (batched-rcp sigmoid) + h writeback to buf pn
#pragma unroll
        for (int h = 0; h < 2; ++h) {
            const int u = 16 * mg + gid + 8 * h;
#pragma unroll
            for (int nt = 0; nt < 2; ++nt)
#pragma unroll
                for (int q = 0; q < 2; ++q) {
                    const int e = 2 * h + q;
                    float a  = 1.0f + ex2n(dac[0][nt][e]);
                    float bb = 1.0f + ex2n(dac[1][nt][e]);
                    float cq = 1.0f + ex2n(dac[3][nt][e]);
                    float ab = a * bb, bc = bb * cq, ac = a * cq;
                    float r  = frcp(ab * cq);
                    float si = bc * r, sf = ac * r, so = ab * r;
                    float cc = fmaxf(dac[2][nt][e], 0.0f);
                    float c  = sf * cst[h][nt][q] + si * cc;
                    cst[h][nt][q] = c;
                    float hv = so * fmaxf(c, 0.0f);
                    hrg[h][nt][q] = hv;
                    int rr = 8 * nt + 2 * tig + q;
                    float hh = bhi(hv);
                    hsm[rr * HSTR + pn * 64 + u]      = __float2bfloat16_rn(hv);
                    hsm[rr * HSTR + pn * 64 + 32 + u] = __float2bfloat16_rn(hv - hh);
                }
        }
        // next iteration's __syncthreads covers visibility
    }

    // ---- output heads
    __syncthreads();
    float* h32 = (float*)(SMEM + HBYTES);   // x region dead: [16][32] fp32
#pragma unroll
    for (int h = 0; h < 2; ++h) {
        const int u = 16 * mg + gid + 8 * h;
#pragma unroll
        for (int nt = 0; nt < 2; ++nt)
#pragma unroll
            for (int q = 0; q < 2; ++q) {
                int rr = 8 * nt + 2 * tig + q;
                h32[rr * 32 + u] = hrg[h][nt][q];
            }
    }
    __syncthreads();

    for (int idx = tid; idx < CROWS * DD; idx += 64) {
        int rr = idx / DD, d = idx - rr * DD;
        const float* hr = h32 + rr * 32;
        float aL = b1[d], aA = b2[d];
#pragma unroll
        for (int u = 0; u < 32; ++u) {
            float hu = hr[u];
            aL = fmaf(hu, W1[u * DD + d], aL);
            aA = fmaf(hu, W2[u * DD + d], aA);
        }
        size_t grow = (size_t)blockIdx.x * CROWS + rr;
        out[grow * DD + d] = aL;
        out[(8192 + grow) * DD + d] = aA;
    }
}

extern "C" void kernel_launch(void* const* d_in, const int* in_sizes, int n_in,
                              void* d_out, int out_size) {
    const float* x  = (const float*)d_in[0];
    const float* W  = (const float*)d_in[1];
    const float* U  = (const float*)d_in[2];
    const float* b  = (const float*)d_in[3];
    const float* W1 = (const float*)d_in[4];
    const float* b1 = (const float*)d_in[5];
    const float* W2 = (const float*)d_in[6];
    const float* b2 = (const float*)d_in[7];
    float* out = (float*)d_out;

    // 8192 rows / 16 per CTA = 512 CTAs, 64 threads (2 warps)
    lstm_mma4_kernel<<<512, 64>>>(x, W, U, b, W1, b1, W2, b2, out);
}

// round 10
// speedup vs baseline: 1.3713x; 1.3713x over previous
#include <cuda_runtime.h>
#include <cuda_fp16.h>
#include <cstdint>

// lstm_model_8873402433789 R10 — mma.sync fp16 LSTM, 48 MMAs/warp-step.
// Weights: exact fp16 hi/lo split (lo scaled x1024, separate accumulator).
// Activations: single fp16 (incoherent per-step rounding ~2^-11).
// 128 CTAs x 64 rows, 8 warps, single pair-barrier per step, private x.

#define TT 200
#define ROWS 64
#define DD 60
#define WSTR 104   // weight row stride (halfs): 208B = 13x16B (ldsm conflict-free)
#define HSTR 72    // h row stride: 144B = 9x16B ; buf0 k0-31, buf1 k32-63
#define XSTR 40    // x private row stride: 80B = 5x16B ; buf0 k0-15, buf1 k16-31

static __device__ __forceinline__ uint32_t s2u(const void* p) {
    uint32_t a;
    asm("{ .reg .u64 t; cvta.to.shared.u64 t, %1; cvt.u32.u64 %0, t; }"
        : "=r"(a) : "l"(p));
    return a;
}
static __device__ __forceinline__ uint32_t hpack(float a, float b) {
    __half2 t = make_half2(__float2half_rn(a), __float2half_rn(b));
    return *(uint32_t*)&t;
}
static __device__ __forceinline__ float ex2n(float g) {   // exp(-g)
    float e;
    asm("ex2.approx.f32 %0, %1;" : "=f"(e) : "f"(-1.4426950408889634f * g));
    return e;
}
static __device__ __forceinline__ float frcp(float a) {
    float r;
    asm("rcp.approx.f32 %0, %1;" : "=f"(r) : "f"(a));
    return r;
}
static __device__ __forceinline__ void ldsm4(uint32_t* r, uint32_t addr) {
    asm volatile("ldmatrix.sync.aligned.m8n8.x4.shared.b16 {%0,%1,%2,%3}, [%4];"
                 : "=r"(r[0]), "=r"(r[1]), "=r"(r[2]), "=r"(r[3]) : "r"(addr));
}
static __device__ __forceinline__ void mma16816(float* d, const uint32_t* a,
                                                const uint32_t* b) {
    asm volatile(
        "mma.sync.aligned.m16n8k16.row.col.f32.f16.f16.f32 "
        "{%0,%1,%2,%3}, {%4,%5,%6,%7}, {%8,%9}, {%0,%1,%2,%3};"
        : "+f"(d[0]), "+f"(d[1]), "+f"(d[2]), "+f"(d[3])
        : "r"(a[0]), "r"(a[1]), "r"(a[2]), "r"(a[3]), "r"(b[0]), "r"(b[1]));
}

__global__ void __launch_bounds__(256, 1) lstm_fp16_kernel(
    const float* __restrict__ x,  const float* __restrict__ W,
    const float* __restrict__ U,  const float* __restrict__ b,
    const float* __restrict__ W1, const float* __restrict__ b1,
    const float* __restrict__ W2, const float* __restrict__ b2,
    float* __restrict__ out)
{
    __shared__ __align__(16) __half wsm[128 * WSTR];        // weights (init) / h32 (heads)
    __shared__ __align__(16) __half hsm[ROWS * HSTR];       // h, double buffered
    __shared__ __align__(16) __half xpr[8 * 16 * XSTR];     // x, per-warp private, dbl buf

    const int tid = threadIdx.x;
    const int l   = tid & 31;
    const int w   = tid >> 5;
    const int gid = l >> 2, tig = l & 3;
    const int mg  = w & 1;        // unit half
    const int ng  = w >> 1;       // row quarter == pair id

    // ---- weights: cols [hi: U k0-31 | W k32-47][lo*1024: U k48-79 | W k80-95]
    for (int idx = tid; idx < 128 * 96; idx += 256) {
        int g = idx / 96, k = idx - g * 96;
        if (k < 48) {
            float src = (k < 32) ? U[k * 128 + g] : W[(k - 32) * 128 + g];
            wsm[g * WSTR + k] = __float2half_rn(src);
        } else {
            int kk = k - 48;
            float src = (kk < 32) ? U[kk * 128 + g] : W[(kk - 32) * 128 + g];
            float hi = __half2float(__float2half_rn(src));
            wsm[g * WSTR + k] = __float2half_rn((src - hi) * 1024.0f);
        }
    }
    __syncthreads();

    // ---- A fragments: afr[mt][0-2 hi k0-15,k16-31,k32-47 | 3-5 lo]
    const uint32_t wsmu = s2u(wsm);
    uint32_t afr[4][6][4];
    {
        int laneRow = (l & 7) + 8 * ((l >> 3) & 1);
        int laneK   = 8 * (l >> 4);
#pragma unroll
        for (int mt = 0; mt < 4; ++mt) {
            int Gmt = 32 * mt + 16 * mg;
#pragma unroll
            for (int ks = 0; ks < 6; ++ks)
                ldsm4(afr[mt][ks], wsmu + ((Gmt + laneRow) * WSTR + 16 * ks + laneK) * 2);
        }
    }
    float bv[4][2];
#pragma unroll
    for (int mt = 0; mt < 4; ++mt) {
        bv[mt][0] = b[32 * mt + 16 * mg + gid];
        bv[mt][1] = b[32 * mt + 16 * mg + gid + 8];
    }

    // ---- init h buf0 = 0
    for (int idx = tid; idx < ROWS * 32; idx += 256) {
        int rr = idx >> 5, cc = idx & 31;
        hsm[rr * HSTR + cc] = __float2half_rn(0.0f);
    }
    // ---- stage x(0) privately (fp16, 16 halfs/row), prefetch x(1)
    const int prow = l >> 1, pseg = l & 1;   // 16 rows x 2 segs of 8 feats
    const float4* xg = (const float4*)(x +
        ((size_t)blockIdx.x * ROWS + 16 * ng + prow) * (TT * 16) + pseg * 8);
    __half* xmy = xpr + (w * 16 + prow) * XSTR;
    {
        float4 v0 = xg[0], v1 = xg[1];
        *(uint4*)(xmy + pseg * 8) =
            make_uint4(hpack(v0.x, v0.y), hpack(v0.z, v0.w),
                       hpack(v1.x, v1.y), hpack(v1.z, v1.w));
    }
    float4 pf0 = xg[4], pf1 = xg[5];
    __syncthreads();

    const uint32_t hbu = s2u(hsm);
    const uint32_t xbu = s2u(xpr + w * 16 * XSTR);
    const int lr8 = l & 7, lq = (l >> 3) & 3;
    const int bar = 1 + ng;

    // x fragment (both nt in one ldsm4): rows 8*(l>>4)+lr8, col 8*((l>>3)&1)
    const uint32_t xfoff = ((8 * (l >> 4) + lr8) * XSTR + 8 * ((l >> 3) & 1)) * 2;
    uint32_t xf[4];
    ldsm4(xf, xbu + xfoff);      // regs 0,1 = nt0 tile, 2,3 = nt1 tile

    float cst[2][2][2], hrg[2][2][2];
#pragma unroll
    for (int i = 0; i < 2; ++i)
#pragma unroll
        for (int j = 0; j < 2; ++j)
#pragma unroll
            for (int k = 0; k < 2; ++k) { cst[i][j][k] = 0.0f; hrg[i][j][k] = 0.0f; }

#pragma unroll 1
    for (int t = 0; t < TT; ++t) {
        const int p = t & 1, pn = p ^ 1;

        // ---- x-MMAs pre-barrier (private xf): hi->dac, lo->daclo
        float dac[4][2][4], daclo[4][2][4];
#pragma unroll
        for (int mt = 0; mt < 4; ++mt)
#pragma unroll
            for (int nt = 0; nt < 2; ++nt) {
                dac[mt][nt][0] = bv[mt][0]; dac[mt][nt][1] = bv[mt][0];
                dac[mt][nt][2] = bv[mt][1]; dac[mt][nt][3] = bv[mt][1];
                daclo[mt][nt][0] = 0.0f; daclo[mt][nt][1] = 0.0f;
                daclo[mt][nt][2] = 0.0f; daclo[mt][nt][3] = 0.0f;
            }
#pragma unroll
        for (int mt = 0; mt < 4; ++mt)
#pragma unroll
            for (int nt = 0; nt < 2; ++nt) {
                mma16816(dac[mt][nt],   afr[mt][2], &xf[2 * nt]);  // Whi . x
                mma16816(daclo[mt][nt], afr[mt][5], &xf[2 * nt]);  // Wlo . x
            }

        // ---- pair barrier: partner's h(t) visible
        asm volatile("bar.sync %0, %1;" :: "r"(bar), "r"(64) : "memory");

        // ---- h fragments (buf p) + h-MMAs
        uint32_t bh[2][4];
#pragma unroll
        for (int nt = 0; nt < 2; ++nt)
            ldsm4(bh[nt], hbu + ((16 * ng + nt * 8 + lr8) * HSTR + p * 32 + lq * 8) * 2);
#pragma unroll
        for (int mt = 0; mt < 4; ++mt)
#pragma unroll
            for (int nt = 0; nt < 2; ++nt) {
                mma16816(dac[mt][nt],   afr[mt][0], &bh[nt][0]);   // Uhi . h k0-15
                mma16816(dac[mt][nt],   afr[mt][1], &bh[nt][2]);   // Uhi . h k16-31
                mma16816(daclo[mt][nt], afr[mt][3], &bh[nt][0]);   // Ulo . h
                mma16816(daclo[mt][nt], afr[mt][4], &bh[nt][2]);
            }

        // ---- stage x(t+1) -> buf pn; prefetch x(t+2); reload xf
        {
            *(uint4*)(xmy + pn * 16 + pseg * 8) =
                make_uint4(hpack(pf0.x, pf0.y), hpack(pf0.z, pf0.w),
                           hpack(pf1.x, pf1.y), hpack(pf1.z, pf1.w));
            int tn = (t + 2 < TT) ? t + 2 : TT - 1;
            pf0 = xg[tn * 4]; pf1 = xg[tn * 4 + 1];
            __syncwarp();
            ldsm4(xf, xbu + pn * 32 + xfoff);
        }

        // ---- state update (g = dac + daclo*2^-10), batched-rcp sigmoid
#pragma unroll
        for (int h = 0; h < 2; ++h) {
            const int u = 16 * mg + gid + 8 * h;
#pragma unroll
            for (int nt = 0; nt < 2; ++nt)
#pragma unroll
                for (int q = 0; q < 2; ++q) {
                    const int e = 2 * h + q;
                    const float S = 9.765625e-4f;   // 2^-10
                    float gi = fmaf(daclo[0][nt][e], S, dac[0][nt][e]);
                    float gf = fmaf(daclo[1][nt][e], S, dac[1][nt][e]);
                    float gc = fmaf(daclo[2][nt][e], S, dac[2][nt][e]);
                    float go = fmaf(daclo[3][nt][e], S, dac[3][nt][e]);
                    float a  = 1.0f + ex2n(gi);
                    float bb = 1.0f + ex2n(gf);
                    float cq = 1.0f + ex2n(go);
                    float ab = a * bb, bc = bb * cq, ac = a * cq;
                    float r  = frcp(ab * cq);
                    float si = bc * r, sf = ac * r, so = ab * r;
                    float cc = fmaxf(gc, 0.0f);
                    float c  = sf * cst[h][nt][q] + si * cc;
                    cst[h][nt][q] = c;
                    float hv = so * fmaxf(c, 0.0f);
                    hrg[h][nt][q] = hv;
                    int rr = 16 * ng + 8 * nt + 2 * tig + q;
                    hsm[rr * HSTR + pn * 32 + u] = __float2half_rn(hv);
                }
        }
        // next iteration's bar.sync covers h visibility
    }

    // ---- output heads: reuse wsm as fp32 h buffer [64][32]
    __syncthreads();
    float* h32 = (float*)wsm;
#pragma unroll
    for (int h = 0; h < 2; ++h) {
        const int u = 16 * mg + gid + 8 * h;
#pragma unroll
        for (int nt = 0; nt < 2; ++nt)
#pragma unroll
            for (int q = 0; q < 2; ++q) {
                int rr = 16 * ng + 8 * nt + 2 * tig + q;
                h32[rr * 32 + u] = hrg[h][nt][q];
            }
    }
    __syncthreads();

    for (int idx = tid; idx < ROWS * DD; idx += 256) {
        int rr = idx / DD, d = idx - rr * DD;
        const float* hr = h32 + rr * 32;
        float aL = b1[d], aA = b2[d];
#pragma unroll
        for (int u = 0; u < 32; ++u) {
            float hu = hr[u];
            aL = fmaf(hu, W1[u * DD + d], aL);
            aA = fmaf(hu, W2[u * DD + d], aA);
        }
        size_t grow = (size_t)blockIdx.x * ROWS + rr;
        out[grow * DD + d] = aL;
        out[(8192 + grow) * DD + d] = aA;
    }
}

extern "C" void kernel_launch(void* const* d_in, const int* in_sizes, int n_in,
                              void* d_out, int out_size) {
    const float* x  = (const float*)d_in[0];
    const float* W  = (const float*)d_in[1];
    const float* U  = (const float*)d_in[2];
    const float* b  = (const float*)d_in[3];
    const float* W1 = (const float*)d_in[4];
    const float* b1 = (const float*)d_in[5];
    const float* W2 = (const float*)d_in[6];
    const float* b2 = (const float*)d_in[7];
    float* out = (float*)d_out;

    lstm_fp16_kernel<<<128, 256>>>(x, W, U, b, W1, b1, W2, b2, out);
}

// round 11
// speedup vs baseline: 2.0678x; 1.5079x over previous
#include <cuda_runtime.h>
#include <cuda_fp16.h>
#include <cstdint>

// lstm_model_8873402433789 R11 — mma.sync pure-fp16 LSTM, 24 MMAs/warp-step.
// Weights single fp16 (no lo compensation), activations fp16, fp32 accum.
// tanh.approx-based sigmoid (3 MUFU/element). 128 CTAs x 64 rows, 8 warps,
// single pair-barrier per step, warp-private double-buffered x.

#define TT 200
#define ROWS 64
#define DD 60
#define WSTR 56    // weight row stride (halfs): 112B = 7x16B (ldsm conflict-free)
#define HSTR 72    // h row stride: buf0 k0-31, buf1 k32-63
#define XSTR 40    // x private row stride: buf0 k0-15, buf1 k16-31

static __device__ __forceinline__ uint32_t s2u(const void* p) {
    uint32_t a;
    asm("{ .reg .u64 t; cvta.to.shared.u64 t, %1; cvt.u32.u64 %0, t; }"
        : "=r"(a) : "l"(p));
    return a;
}
static __device__ __forceinline__ uint32_t hpack(float a, float b) {
    __half2 t = make_half2(__float2half_rn(a), __float2half_rn(b));
    return *(uint32_t*)&t;
}
static __device__ __forceinline__ float sigt(float g) {   // sigmoid via MUFU.TANH
    float t;
    asm("tanh.approx.f32 %0, %1;" : "=f"(t) : "f"(0.5f * g));
    return fmaf(0.5f, t, 0.5f);
}
static __device__ __forceinline__ void ldsm4(uint32_t* r, uint32_t addr) {
    asm volatile("ldmatrix.sync.aligned.m8n8.x4.shared.b16 {%0,%1,%2,%3}, [%4];"
                 : "=r"(r[0]), "=r"(r[1]), "=r"(r[2]), "=r"(r[3]) : "r"(addr));
}
static __device__ __forceinline__ void mma16816(float* d, const uint32_t* a,
                                                const uint32_t* b) {
    asm volatile(
        "mma.sync.aligned.m16n8k16.row.col.f32.f16.f16.f32 "
        "{%0,%1,%2,%3}, {%4,%5,%6,%7}, {%8,%9}, {%0,%1,%2,%3};"
        : "+f"(d[0]), "+f"(d[1]), "+f"(d[2]), "+f"(d[3])
        : "r"(a[0]), "r"(a[1]), "r"(a[2]), "r"(a[3]), "r"(b[0]), "r"(b[1]));
}

__global__ void __launch_bounds__(256, 1) lstm_fp16b_kernel(
    const float* __restrict__ x,  const float* __restrict__ W,
    const float* __restrict__ U,  const float* __restrict__ b,
    const float* __restrict__ W1, const float* __restrict__ b1,
    const float* __restrict__ W2, const float* __restrict__ b2,
    float* __restrict__ out)
{
    __shared__ __align__(16) __half wsm[128 * WSTR];        // weights / h32 (heads)
    __shared__ __align__(16) __half hsm[ROWS * HSTR];       // h, double buffered
    __shared__ __align__(16) __half xpr[8 * 16 * XSTR];     // x, warp-private, dbl buf

    const int tid = threadIdx.x;
    const int l   = tid & 31;
    const int w   = tid >> 5;
    const int gid = l >> 2, tig = l & 3;
    const int mg  = w & 1;        // unit half
    const int ng  = w >> 1;       // row quarter == pair id

    // ---- weights (hi only): cols [U k0-31 | W k32-47]
    for (int idx = tid; idx < 128 * 48; idx += 256) {
        int g = idx / 48, k = idx - g * 48;
        float src = (k < 32) ? U[k * 128 + g] : W[(k - 32) * 128 + g];
        wsm[g * WSTR + k] = __float2half_rn(src);
    }
    __syncthreads();

    // ---- A fragments: afr[mt][ks 0,1 = h k0-15,k16-31 ; 2 = x k32-47]
    const uint32_t wsmu = s2u(wsm);
    uint32_t afr[4][3][4];
    {
        int laneRow = (l & 7) + 8 * ((l >> 3) & 1);
        int laneK   = 8 * (l >> 4);
#pragma unroll
        for (int mt = 0; mt < 4; ++mt) {
            int Gmt = 32 * mt + 16 * mg;
#pragma unroll
            for (int ks = 0; ks < 3; ++ks)
                ldsm4(afr[mt][ks], wsmu + ((Gmt + laneRow) * WSTR + 16 * ks + laneK) * 2);
        }
    }
    float bv[4][2];
#pragma unroll
    for (int mt = 0; mt < 4; ++mt) {
        bv[mt][0] = b[32 * mt + 16 * mg + gid];
        bv[mt][1] = b[32 * mt + 16 * mg + gid + 8];
    }

    // ---- init h buf0 = 0
    for (int idx = tid; idx < ROWS * 32; idx += 256) {
        int rr = idx >> 5, cc = idx & 31;
        hsm[rr * HSTR + cc] = __float2half_rn(0.0f);
    }
    // ---- stage x(0) privately, prefetch x(1)
    const int prow = l >> 1, pseg = l & 1;
    const float4* xg = (const float4*)(x +
        ((size_t)blockIdx.x * ROWS + 16 * ng + prow) * (TT * 16) + pseg * 8);
    __half* xmy = xpr + (w * 16 + prow) * XSTR;
    {
        float4 v0 = xg[0], v1 = xg[1];
        *(uint4*)(xmy + pseg * 8) =
            make_uint4(hpack(v0.x, v0.y), hpack(v0.z, v0.w),
                       hpack(v1.x, v1.y), hpack(v1.z, v1.w));
    }
    float4 pf0 = xg[4], pf1 = xg[5];
    __syncthreads();

    const uint32_t hbu = s2u(hsm);
    const uint32_t xbu = s2u(xpr + w * 16 * XSTR);
    const int lr8 = l & 7, lq = (l >> 3) & 3;
    const int bar = 1 + ng;

    const uint32_t xfoff = ((8 * (l >> 4) + lr8) * XSTR + 8 * ((l >> 3) & 1)) * 2;
    uint32_t xf[4];
    ldsm4(xf, xbu + xfoff);      // regs 0,1 = nt0 tile, 2,3 = nt1 tile

    float cst[2][2][2], hrg[2][2][2];
#pragma unroll
    for (int i = 0; i < 2; ++i)
#pragma unroll
        for (int j = 0; j < 2; ++j)
#pragma unroll
            for (int k = 0; k < 2; ++k) { cst[i][j][k] = 0.0f; hrg[i][j][k] = 0.0f; }

#pragma unroll 1
    for (int t = 0; t < TT; ++t) {
        const int p = t & 1, pn = p ^ 1;

        // ---- x-MMAs pre-barrier (private xf)
        float dac[4][2][4];
#pragma unroll
        for (int mt = 0; mt < 4; ++mt)
#pragma unroll
            for (int nt = 0; nt < 2; ++nt) {
                dac[mt][nt][0] = bv[mt][0]; dac[mt][nt][1] = bv[mt][0];
                dac[mt][nt][2] = bv[mt][1]; dac[mt][nt][3] = bv[mt][1];
            }
#pragma unroll
        for (int mt = 0; mt < 4; ++mt)
#pragma unroll
            for (int nt = 0; nt < 2; ++nt)
                mma16816(dac[mt][nt], afr[mt][2], &xf[2 * nt]);   // W . x

        // ---- pair barrier: partner's h(t) visible
        asm volatile("bar.sync %0, %1;" :: "r"(bar), "r"(64) : "memory");

        // ---- h fragments (buf p) + h-MMAs
        uint32_t bh[2][4];
#pragma unroll
        for (int nt = 0; nt < 2; ++nt)
            ldsm4(bh[nt], hbu + ((16 * ng + nt * 8 + lr8) * HSTR + p * 32 + lq * 8) * 2);
#pragma unroll
        for (int mt = 0; mt < 4; ++mt)
#pragma unroll
            for (int nt = 0; nt < 2; ++nt) {
                mma16816(dac[mt][nt], afr[mt][0], &bh[nt][0]);    // U . h k0-15
                mma16816(dac[mt][nt], afr[mt][1], &bh[nt][2]);    // U . h k16-31
            }

        // ---- stage x(t+1) -> buf pn; prefetch x(t+2); reload xf
        {
            *(uint4*)(xmy + pn * 16 + pseg * 8) =
                make_uint4(hpack(pf0.x, pf0.y), hpack(pf0.z, pf0.w),
                           hpack(pf1.x, pf1.y), hpack(pf1.z, pf1.w));
            int tn = (t + 2 < TT) ? t + 2 : TT - 1;
            pf0 = xg[tn * 4]; pf1 = xg[tn * 4 + 1];
            __syncwarp();
            ldsm4(xf, xbu + pn * 32 + xfoff);
        }

        // ---- state update: tanh-sigmoid (3 MUFU/element)
#pragma unroll
        for (int h = 0; h < 2; ++h) {
            const int u = 16 * mg + gid + 8 * h;
#pragma unroll
            for (int nt = 0; nt < 2; ++nt)
#pragma unroll
                for (int q = 0; q < 2; ++q) {
                    const int e = 2 * h + q;
                    float si = sigt(dac[0][nt][e]);
                    float sf = sigt(dac[1][nt][e]);
                    float so = sigt(dac[3][nt][e]);
                    float cc = fmaxf(dac[2][nt][e], 0.0f);
                    float c  = sf * cst[h][nt][q] + si * cc;
                    cst[h][nt][q] = c;
                    float hv = so * fmaxf(c, 0.0f);
                    hrg[h][nt][q] = hv;
                    int rr = 16 * ng + 8 * nt + 2 * tig + q;
                    hsm[rr * HSTR + pn * 32 + u] = __float2half_rn(hv);
                }
        }
        // next iteration's bar.sync covers h visibility
    }

    // ---- output heads: reuse wsm as fp32 h buffer [64][32]
    __syncthreads();
    float* h32 = (float*)wsm;
#pragma unroll
    for (int h = 0; h < 2; ++h) {
        const int u = 16 * mg + gid + 8 * h;
#pragma unroll
        for (int nt = 0; nt < 2; ++nt)
#pragma unroll
            for (int q = 0; q < 2; ++q) {
                int rr = 16 * ng + 8 * nt + 2 * tig + q;
                h32[rr * 32 + u] = hrg[h][nt][q];
            }
    }
    __syncthreads();

    for (int idx = tid; idx < ROWS * DD; idx += 256) {
        int rr = idx / DD, d = idx - rr * DD;
        const float* hr = h32 + rr * 32;
        float aL = b1[d], aA = b2[d];
#pragma unroll
        for (int u = 0; u < 32; ++u) {
            float hu = hr[u];
            aL = fmaf(hu, W1[u * DD + d], aL);
            aA = fmaf(hu, W2[u * DD + d], aA);
        }
        size_t grow = (size_t)blockIdx.x * ROWS + rr;
        out[grow * DD + d] = aL;
        out[(8192 + grow) * DD + d] = aA;
    }
}

extern "C" void kernel_launch(void* const* d_in, const int* in_sizes, int n_in,
                              void* d_out, int out_size) {
    const float* x  = (const float*)d_in[0];
    const float* W  = (const float*)d_in[1];
    const float* U  = (const float*)d_in[2];
    const float* b  = (const float*)d_in[3];
    const float* W1 = (const float*)d_in[4];
    const float* b1 = (const float*)d_in[5];
    const float* W2 = (const float*)d_in[6];
    const float* b2 = (const float*)d_in[7];
    float* out = (float*)d_out;

    lstm_fp16b_kernel<<<128, 256>>>(x, W, U, b, W1, b1, W2, b2, out);
}

// round 12
// speedup vs baseline: 2.2103x; 1.0689x over previous
#include <cuda_runtime.h>
#include <cuda_fp16.h>
#include <cstdint>

// lstm_model_8873402433789 R12 — fp16 mma.sync LSTM, 8 rows/warp, 2048 warps.
// 512 CTAs x 128 thr (4 warps = 2 pairs x 8 rows), all co-resident (<=128 regs,
// 4 CTAs/SM) -> ~3.5 warps/SMSP to hide the per-step latency chain.
// 12 MMAs/warp-step, tanh-sigmoid, single pair-barrier, private x.

#define TT 200
#define CROWS 16    // rows per CTA
#define DD 60
#define WSTR 56     // weight row stride (halfs)
#define HSTR 72     // h row stride: buf0 k0-31, buf1 k32-63
#define XSTR 40     // x row stride: buf0 k0-15, buf1 k16-31

static __device__ __forceinline__ uint32_t s2u(const void* p) {
    uint32_t a;
    asm("{ .reg .u64 t; cvta.to.shared.u64 t, %1; cvt.u32.u64 %0, t; }"
        : "=r"(a) : "l"(p));
    return a;
}
static __device__ __forceinline__ uint32_t hpack(float a, float b) {
    __half2 t = make_half2(__float2half_rn(a), __float2half_rn(b));
    return *(uint32_t*)&t;
}
static __device__ __forceinline__ float sigt(float g) {   // sigmoid via MUFU.TANH
    float t;
    asm("tanh.approx.f32 %0, %1;" : "=f"(t) : "f"(0.5f * g));
    return fmaf(0.5f, t, 0.5f);
}
static __device__ __forceinline__ void ldsm4(uint32_t* r, uint32_t addr) {
    asm volatile("ldmatrix.sync.aligned.m8n8.x4.shared.b16 {%0,%1,%2,%3}, [%4];"
                 : "=r"(r[0]), "=r"(r[1]), "=r"(r[2]), "=r"(r[3]) : "r"(addr));
}
static __device__ __forceinline__ void ldsm2(uint32_t* r, uint32_t addr) {
    asm volatile("ldmatrix.sync.aligned.m8n8.x2.shared.b16 {%0,%1}, [%2];"
                 : "=r"(r[0]), "=r"(r[1]) : "r"(addr));
}
static __device__ __forceinline__ void mma16816(float* d, const uint32_t* a,
                                                const uint32_t* b) {
    asm volatile(
        "mma.sync.aligned.m16n8k16.row.col.f32.f16.f16.f32 "
        "{%0,%1,%2,%3}, {%4,%5,%6,%7}, {%8,%9}, {%0,%1,%2,%3};"
        : "+f"(d[0]), "+f"(d[1]), "+f"(d[2]), "+f"(d[3])
        : "r"(a[0]), "r"(a[1]), "r"(a[2]), "r"(a[3]), "r"(b[0]), "r"(b[1]));
}

__global__ void __launch_bounds__(128, 4) lstm_fp16c_kernel(
    const float* __restrict__ x,  const float* __restrict__ W,
    const float* __restrict__ U,  const float* __restrict__ b,
    const float* __restrict__ W1, const float* __restrict__ b1,
    const float* __restrict__ W2, const float* __restrict__ b2,
    float* __restrict__ out)
{
    __shared__ __align__(16) __half wsm[128 * WSTR];        // weights / h32 (heads)
    __shared__ __align__(16) __half hsm[CROWS * HSTR];      // h, double buffered
    __shared__ __align__(16) __half xpr[4 * 8 * XSTR];      // x, warp-private, dbl buf

    const int tid = threadIdx.x;
    const int l   = tid & 31;
    const int w   = tid >> 5;        // 0..3
    const int gid = l >> 2, tig = l & 3;
    const int mg  = w & 1;           // unit half
    const int ng  = w >> 1;          // pair id (8-row group), 0..1

    // ---- weights: cols [U k0-31 | W k32-47], fp16
    for (int idx = tid; idx < 128 * 48; idx += 128) {
        int g = idx / 48, k = idx - g * 48;
        float src = (k < 32) ? U[k * 128 + g] : W[(k - 32) * 128 + g];
        wsm[g * WSTR + k] = __float2half_rn(src);
    }
    __syncthreads();

    // ---- A fragments: afr[mt][ks 0,1 = h k0-15,k16-31 ; 2 = x]
    const uint32_t wsmu = s2u(wsm);
    uint32_t afr[4][3][4];
    {
        int laneRow = (l & 7) + 8 * ((l >> 3) & 1);
        int laneK   = 8 * (l >> 4);
#pragma unroll
        for (int mt = 0; mt < 4; ++mt) {
            int Gmt = 32 * mt + 16 * mg;
#pragma unroll
            for (int ks = 0; ks < 3; ++ks)
                ldsm4(afr[mt][ks], wsmu + ((Gmt + laneRow) * WSTR + 16 * ks + laneK) * 2);
        }
    }
    float bv[4][2];
#pragma unroll
    for (int mt = 0; mt < 4; ++mt) {
        bv[mt][0] = b[32 * mt + 16 * mg + gid];
        bv[mt][1] = b[32 * mt + 16 * mg + gid + 8];
    }

    // ---- init h buf0 = 0
    for (int idx = tid; idx < CROWS * 32; idx += 128) {
        int rr = idx >> 5, cc = idx & 31;
        hsm[rr * HSTR + cc] = __float2half_rn(0.0f);
    }
    // ---- stage x(0) privately (8 rows x 16 feats), prefetch x(1)
    const int prow = l >> 2, pseg = l & 3;   // 8 rows x 4 float4-segs
    const float* xrow = x + ((size_t)blockIdx.x * CROWS + 8 * ng + prow) * (TT * 16);
    const float4* xg = (const float4*)(xrow) + pseg;   // step t at xg[4*t]
    __half* xmy = xpr + (w * 8 + prow) * XSTR;
    {
        float4 v = xg[0];
        *(uint2*)(xmy + pseg * 4) = make_uint2(hpack(v.x, v.y), hpack(v.z, v.w));
    }
    float4 pf = xg[4];    // x(1)
    __syncthreads();

    const uint32_t hbu = s2u(hsm);
    const uint32_t xbu = s2u(xpr + w * 8 * XSTR);
    const int lr8 = l & 7;
    const int bar = 1 + ng;

    // x frag (x2, lanes 0-15): row lr8, col 8*((l>>3)&1)
    const uint32_t xfoff = (lr8 * XSTR + 8 * ((l >> 3) & 1)) * 2;
    uint32_t xf[2];
    ldsm2(xf, xbu + xfoff);

    float cst[2][2], hrg[2][2];
#pragma unroll
    for (int i = 0; i < 2; ++i)
#pragma unroll
        for (int j = 0; j < 2; ++j) { cst[i][j] = 0.0f; hrg[i][j] = 0.0f; }

#pragma unroll 1
    for (int t = 0; t < TT; ++t) {
        const int p = t & 1, pn = p ^ 1;

        // ---- x-MMAs pre-barrier (private xf)
        float dac[4][4];
#pragma unroll
        for (int mt = 0; mt < 4; ++mt) {
            dac[mt][0] = bv[mt][0]; dac[mt][1] = bv[mt][0];
            dac[mt][2] = bv[mt][1]; dac[mt][3] = bv[mt][1];
        }
#pragma unroll
        for (int mt = 0; mt < 4; ++mt)
            mma16816(dac[mt], afr[mt][2], xf);          // W . x

        // ---- pair barrier: partner's h(t) visible
        asm volatile("bar.sync %0, %1;" :: "r"(bar), "r"(64) : "memory");

        // ---- h fragment (8 rows x 32 k, one ldsm4) + h-MMAs
        uint32_t bh[4];
        ldsm4(bh, hbu + ((8 * ng + lr8) * HSTR + p * 32 + 8 * (l >> 3)) * 2);
#pragma unroll
        for (int mt = 0; mt < 4; ++mt) {
            mma16816(dac[mt], afr[mt][0], &bh[0]);      // U . h k0-15
            mma16816(dac[mt], afr[mt][1], &bh[2]);      // U . h k16-31
        }

        // ---- stage x(t+1) -> buf pn; prefetch x(t+2); reload xf
        {
            *(uint2*)(xmy + pn * 16 + pseg * 4) =
                make_uint2(hpack(pf.x, pf.y), hpack(pf.z, pf.w));
            int tn = (t + 2 < TT) ? t + 2 : TT - 1;
            pf = xg[tn * 4];
            __syncwarp();
            ldsm2(xf, xbu + pn * 32 + xfoff);
        }

        // ---- state update: tanh-sigmoid, 4 elements/thread
#pragma unroll
        for (int h = 0; h < 2; ++h) {
            const int u = 16 * mg + gid + 8 * h;
#pragma unroll
            for (int q = 0; q < 2; ++q) {
                const int e = 2 * h + q;
                float si = sigt(dac[0][e]);
                float sf = sigt(dac[1][e]);
                float so = sigt(dac[3][e]);
                float cc = fmaxf(dac[2][e], 0.0f);
                float c  = sf * cst[h][q] + si * cc;
                cst[h][q] = c;
                float hv = so * fmaxf(c, 0.0f);
                hrg[h][q] = hv;
                int rr = 8 * ng + 2 * tig + q;
                hsm[rr * HSTR + pn * 32 + u] = __float2half_rn(hv);
            }
        }
        // next iteration's bar.sync covers h visibility
    }

    // ---- output heads: reuse wsm as fp32 h buffer [16][32]
    __syncthreads();
    float* h32 = (float*)wsm;
#pragma unroll
    for (int h = 0; h < 2; ++h) {
        const int u = 16 * mg + gid + 8 * h;
#pragma unroll
        for (int q = 0; q < 2; ++q) {
            int rr = 8 * ng + 2 * tig + q;
            h32[rr * 32 + u] = hrg[h][q];
        }
    }
    __syncthreads();

    for (int idx = tid; idx < CROWS * DD; idx += 128) {
        int rr = idx / DD, d = idx - rr * DD;
        const float* hr = h32 + rr * 32;
        float aL = b1[d], aA = b2[d];
#pragma unroll
        for (int u = 0; u < 32; ++u) {
            float hu = hr[u];
            aL = fmaf(hu, W1[u * DD + d], aL);
            aA = fmaf(hu, W2[u * DD + d], aA);
        }
        size_t grow = (size_t)blockIdx.x * CROWS + rr;
        out[grow * DD + d] = aL;
        out[(8192 + grow) * DD + d] = aA;
    }
}

extern "C" void kernel_launch(void* const* d_in, const int* in_sizes, int n_in,
                              void* d_out, int out_size) {
    const float* x  = (const float*)d_in[0];
    const float* W  = (const float*)d_in[1];
    const float* U  = (const float*)d_in[2];
    const float* b  = (const float*)d_in[3];
    const float* W1 = (const float*)d_in[4];
    const float* b1 = (const float*)d_in[5];
    const float* W2 = (const float*)d_in[6];
    const float* b2 = (const float*)d_in[7];
    float* out = (float*)d_out;

    // 8192 rows / 16 per CTA = 512 CTAs, 128 threads (4 warps, 2 pairs)
    lstm_fp16c_kernel<<<512, 128>>>(x, W, U, b, W1, b1, W2, b2, out);
}